// round 2
// baseline (speedup 1.0000x reference)
#include <cuda_runtime.h>
#include <cstdint>

#define NN 100000
#define NE 1600000

// Scratch (device globals -- no allocation allowed). 16B-aligned for uint4/float4 access.
__device__ __align__(16) unsigned int g_keys[(size_t)NN * 128];   // 51.2 MB: monotone-encoded max keys
__device__ __align__(16) float        g_h[(size_t)NN * 128];      // 51.2 MB: hidden activations

// ---- order-preserving float<->u32 key encoding ----
// enc is strictly increasing in float order; sentinel 0 decodes to a non-finite
// value -> mapped to 0 (matches the reference's isfinite filter for isolated nodes).
__device__ __forceinline__ unsigned enc_f(float f) {
    unsigned u = __float_as_uint(f);
    return (u & 0x80000000u) ? ~u : (u | 0x80000000u);
}
__device__ __forceinline__ float dec_k(unsigned k) {
    unsigned u = (k & 0x80000000u) ? (k & 0x7FFFFFFFu) : ~k;
    if (((u >> 23) & 0xFFu) == 0xFFu) return 0.0f;   // non-finite (incl. sentinel) -> 0
    return __uint_as_float(u);
}

__global__ void k_init_keys() {
    size_t i = (size_t)blockIdx.x * blockDim.x + threadIdx.x;   // exactly NN*128/4 threads
    ((uint4*)g_keys)[i] = make_uint4(0u, 0u, 0u, 0u);
}

// One warp per edge. Lane l handles channels [4l, 4l+4): float4 gather from the
// source row, then guarded atomicMax on the monotone keys. The pre-read filter is
// race-safe: keys only grow, so a stale (smaller) read can only cause an extra
// atomic, never a skipped necessary one.
template<bool USE_H>
__global__ void __launch_bounds__(256) k_scatter(const float* __restrict__ xin,
                                                 const int* __restrict__ esrc,
                                                 const int* __restrict__ edst) {
    int w = (blockIdx.x * blockDim.x + threadIdx.x) >> 5;
    if (w >= NE) return;
    int lane = threadIdx.x & 31;
    const float* feat = USE_H ? g_h : xin;
    int s = esrc[w];
    int d = edst[w];
    if ((unsigned)s >= NN || (unsigned)d >= NN) return;   // defensive (should never hit)
    float4 v = *(const float4*)(feat + (size_t)s * 128 + lane * 4);
    unsigned* kp = g_keys + (size_t)d * 128 + lane * 4;
    unsigned k0 = enc_f(v.x), k1 = enc_f(v.y), k2 = enc_f(v.z), k3 = enc_f(v.w);
    uint4 cur = *(const uint4*)kp;
    if (k0 > cur.x) atomicMax(kp + 0, k0);
    if (k1 > cur.y) atomicMax(kp + 1, k1);
    if (k2 > cur.z) atomicMax(kp + 2, k2);
    if (k3 > cur.w) atomicMax(kp + 3, k3);
}

// Fused SAGE layer GEMM: out[r, :] = act( dec(keys[r,:]) @ Wl + root[r,:] @ Wr + b )
// A is the virtual [NN, 256] matrix [aggr | root]; K-chunks 0..7 read keys (decoded
// on load), chunks 8..15 read root features. 128xCOUT block tile, 256 threads,
// 8x(COUT/16) register tile per thread, BK=16.
template<int COUT, bool L1>
__global__ void __launch_bounds__(256) k_gemm(const float* __restrict__ xin,
                                              const float* __restrict__ Wl,
                                              const float* __restrict__ Wr,
                                              const float* __restrict__ bias,
                                              float* __restrict__ outp) {
    constexpr int BM = 128, BK = 16;
    constexpr int TM = 8, TN = COUT / 16;
    constexpr int LDA = BM + 4;                 // keeps rows 16B-aligned, staggers banks
    __shared__ float As[BK][LDA];               // A^T tile
    __shared__ float Bs[BK][COUT];

    const float* root = L1 ? xin : g_h;
    float*       out  = L1 ? g_h : outp;

    int tid = threadIdx.x;
    int tx = tid & 15;          // 16 col-groups
    int ty = tid >> 4;          // 16 row-groups
    int rowBase = blockIdx.x * BM;

    float acc[TM][TN];
#pragma unroll
    for (int i = 0; i < TM; i++)
#pragma unroll
        for (int j = 0; j < TN; j++) acc[i][j] = 0.0f;

    for (int kk = 0; kk < 256; kk += BK) {
        bool first = kk < 128;
        int kOff = first ? kk : (kk - 128);

        // --- load A tile (128 rows x 16 k), transposed into As[k][row] ---
#pragma unroll
        for (int it = 0; it < 2; it++) {
            int idx = tid + it * 256;           // 0..511
            int r = idx >> 2;                   // row in tile
            int kq = (idx & 3) * 4;             // k quad
            int grow = rowBase + r;
            float4 v = make_float4(0.f, 0.f, 0.f, 0.f);
            if (grow < NN) {
                if (first) {
                    uint4 u = *(const uint4*)(g_keys + (size_t)grow * 128 + kOff + kq);
                    v.x = dec_k(u.x); v.y = dec_k(u.y); v.z = dec_k(u.z); v.w = dec_k(u.w);
                } else {
                    v = *(const float4*)(root + (size_t)grow * 128 + kOff + kq);
                }
            }
            As[kq + 0][r] = v.x;
            As[kq + 1][r] = v.y;
            As[kq + 2][r] = v.z;
            As[kq + 3][r] = v.w;
        }

        // --- load B tile (16 x COUT) from Wl or Wr ---
        const float* W = first ? Wl : Wr;
        constexpr int BV = BK * COUT / 4;       // float4 count: 512 (COUT=128) / 256 (COUT=64)
#pragma unroll
        for (int it = 0; it < BV / 256; it++) {
            int idx = tid + it * 256;
            int r = idx / (COUT / 4);
            int c = (idx % (COUT / 4)) * 4;
            *(float4*)&Bs[r][c] = *(const float4*)(W + (size_t)(kOff + r) * COUT + c);
        }
        __syncthreads();

        // --- compute ---
#pragma unroll
        for (int k = 0; k < BK; k++) {
            float a[TM], b[TN];
            float4 a0 = *(const float4*)&As[k][ty * TM];
            float4 a1 = *(const float4*)&As[k][ty * TM + 4];
            a[0] = a0.x; a[1] = a0.y; a[2] = a0.z; a[3] = a0.w;
            a[4] = a1.x; a[5] = a1.y; a[6] = a1.z; a[7] = a1.w;
            float4 b0 = *(const float4*)&Bs[k][tx * TN];
            b[0] = b0.x; b[1] = b0.y; b[2] = b0.z; b[3] = b0.w;
            if (TN == 8) {
                float4 b1 = *(const float4*)&Bs[k][tx * TN + 4];
                b[4] = b1.x; b[5] = b1.y; b[6] = b1.z; b[7] = b1.w;
            }
#pragma unroll
            for (int i = 0; i < TM; i++)
#pragma unroll
                for (int j = 0; j < TN; j++)
                    acc[i][j] = fmaf(a[i], b[j], acc[i][j]);
        }
        __syncthreads();
    }

    // --- epilogue: bias (+ ReLU), vectorized stores ---
    float bv[TN];
#pragma unroll
    for (int j = 0; j < TN; j++) bv[j] = bias[tx * TN + j];

#pragma unroll
    for (int i = 0; i < TM; i++) {
        int grow = rowBase + ty * TM + i;
        if (grow < NN) {
            float r[TN];
#pragma unroll
            for (int j = 0; j < TN; j++) {
                float v = acc[i][j] + bv[j];
                r[j] = L1 ? fmaxf(v, 0.0f) : v;
            }
            float* op = out + (size_t)grow * COUT + tx * TN;
#pragma unroll
            for (int j = 0; j < TN; j += 4)
                *(float4*)(op + j) = make_float4(r[j], r[j + 1], r[j + 2], r[j + 3]);
        }
    }
}

extern "C" void kernel_launch(void* const* d_in, const int* in_sizes, int n_in,
                              void* d_out, int out_size) {
    const float* x   = (const float*)d_in[0];
    const int*   ei  = (const int*)d_in[1];     // int64 in reference -> delivered as int32
    const float* W1l = (const float*)d_in[2];
    const float* b1  = (const float*)d_in[3];
    const float* W1r = (const float*)d_in[4];
    const float* W2l = (const float*)d_in[5];
    const float* b2  = (const float*)d_in[6];
    const float* W2r = (const float*)d_in[7];
    float*       out = (float*)d_out;

    const int* esrc = ei;
    const int* edst = ei + NE;

    const int initBlocks    = (NN * 128 / 4) / 256;            // 12500, exact
    const int scatterBlocks = (NE * 32) / 256;                  // 200000, exact
    const int gemmBlocks    = (NN + 127) / 128;                 // 782

    // Layer 1
    k_init_keys<<<initBlocks, 256>>>();
    k_scatter<false><<<scatterBlocks, 256>>>(x, esrc, edst);
    k_gemm<128, true><<<gemmBlocks, 256>>>(x, W1l, W1r, b1, nullptr);

    // Layer 2
    k_init_keys<<<initBlocks, 256>>>();
    k_scatter<true><<<scatterBlocks, 256>>>(nullptr, esrc, edst);
    k_gemm<64, false><<<gemmBlocks, 256>>>(nullptr, W2l, W2r, b2, out);
}

// round 3
// speedup vs baseline: 1.9980x; 1.9980x over previous
#include <cuda_runtime.h>
#include <cstdint>

#define NN 100000
#define NE 1600000
#define SCAN_B 1024
#define NBLK ((NN + SCAN_B - 1) / SCAN_B)   // 98

// Scratch (device globals -- no allocation allowed)
__device__ __align__(16) float g_aggr[(size_t)NN * 128];   // 51.2 MB aggregated (max) features
__device__ __align__(16) float g_h[(size_t)NN * 128];      // 51.2 MB hidden activations
__device__ int g_deg[NN];
__device__ int g_rowStart[NN + 1];
__device__ int g_cursor[NN];
__device__ int g_srcIdx[NE];                                // 6.4 MB CSR column (src) indices
__device__ int g_blockTot[NBLK];

// ---------------- CSR build ----------------
__global__ void k_zero_deg() {
    int i = blockIdx.x * blockDim.x + threadIdx.x;
    if (i < NN) g_deg[i] = 0;
}

__global__ void k_count(const int* __restrict__ edst) {
    int i = blockIdx.x * blockDim.x + threadIdx.x;
    if (i < NE) atomicAdd(&g_deg[edst[i]], 1);
}

// per-block exclusive scan (Hillis-Steele in smem) + block totals
__global__ void __launch_bounds__(SCAN_B) k_scan1() {
    __shared__ int s[SCAN_B];
    int t = threadIdx.x;
    int i = blockIdx.x * SCAN_B + t;
    int v = (i < NN) ? g_deg[i] : 0;
    s[t] = v;
    __syncthreads();
#pragma unroll
    for (int off = 1; off < SCAN_B; off <<= 1) {
        int x = (t >= off) ? s[t - off] : 0;
        __syncthreads();
        s[t] += x;
        __syncthreads();
    }
    if (i < NN) g_rowStart[i] = s[t] - v;            // block-local exclusive
    if (t == SCAN_B - 1) g_blockTot[blockIdx.x] = s[t];
}

__global__ void k_scan2() {                           // 1 block, 128 threads scans 98 totals
    __shared__ int s[128];
    int t = threadIdx.x;
    int v = (t < NBLK) ? g_blockTot[t] : 0;
    s[t] = v;
    __syncthreads();
#pragma unroll
    for (int off = 1; off < 128; off <<= 1) {
        int x = (t >= off) ? s[t - off] : 0;
        __syncthreads();
        s[t] += x;
        __syncthreads();
    }
    if (t < NBLK) g_blockTot[t] = s[t] - v;           // exclusive
}

__global__ void __launch_bounds__(SCAN_B) k_scan3() {
    int i = blockIdx.x * SCAN_B + threadIdx.x;
    if (i < NN) {
        int r = g_rowStart[i] + g_blockTot[blockIdx.x];
        g_rowStart[i] = r;
        g_cursor[i] = r;
    }
    if (i == 0) g_rowStart[NN] = NE;
}

__global__ void k_fill(const int* __restrict__ esrc, const int* __restrict__ edst) {
    int i = blockIdx.x * blockDim.x + threadIdx.x;
    if (i < NE) {
        int p = atomicAdd(&g_cursor[edst[i]], 1);
        g_srcIdx[p] = esrc[i];
    }
}

// ---------------- aggregation: warp per node, gather-max over CSR row ----------------
__device__ __forceinline__ float4 max4(float4 a, float4 b) {
    return make_float4(fmaxf(a.x, b.x), fmaxf(a.y, b.y), fmaxf(a.z, b.z), fmaxf(a.w, b.w));
}

template<bool USE_H>
__global__ void __launch_bounds__(256) k_aggr(const float* __restrict__ xin) {
    int w = (blockIdx.x * blockDim.x + threadIdx.x) >> 5;
    if (w >= NN) return;
    int lane = threadIdx.x & 31;
    const float* feat = USE_H ? g_h : xin;
    int beg = g_rowStart[w];
    int end = g_rowStart[w + 1];
    const float NEG = __int_as_float(0xff800000);    // -inf
    float4 m = make_float4(NEG, NEG, NEG, NEG);
    int e = beg;
    // unroll-4 for MLP against L2 latency
    for (; e + 4 <= end; e += 4) {
        int s0 = g_srcIdx[e + 0], s1 = g_srcIdx[e + 1];
        int s2 = g_srcIdx[e + 2], s3 = g_srcIdx[e + 3];
        float4 v0 = *(const float4*)(feat + (size_t)s0 * 128 + lane * 4);
        float4 v1 = *(const float4*)(feat + (size_t)s1 * 128 + lane * 4);
        float4 v2 = *(const float4*)(feat + (size_t)s2 * 128 + lane * 4);
        float4 v3 = *(const float4*)(feat + (size_t)s3 * 128 + lane * 4);
        m = max4(m, max4(max4(v0, v1), max4(v2, v3)));
    }
    for (; e < end; e++) {
        int s0 = g_srcIdx[e];
        float4 v0 = *(const float4*)(feat + (size_t)s0 * 128 + lane * 4);
        m = max4(m, v0);
    }
    if (beg == end) m = make_float4(0.f, 0.f, 0.f, 0.f);   // isolated node -> 0 (PyG behavior)
    *(float4*)(g_aggr + (size_t)w * 128 + lane * 4) = m;
}

// ---------------- fused SAGE layer GEMM ----------------
// out[r,:] = act( aggr[r,:] @ Wl + root[r,:] @ Wr + b ); A = virtual [NN,256] = [aggr | root]
template<int COUT, bool L1>
__global__ void __launch_bounds__(256) k_gemm(const float* __restrict__ xin,
                                              const float* __restrict__ Wl,
                                              const float* __restrict__ Wr,
                                              const float* __restrict__ bias,
                                              float* __restrict__ outp) {
    constexpr int BM = 128, BK = 16;
    constexpr int TM = 8, TN = COUT / 16;
    constexpr int LDA = BM + 4;
    __shared__ float As[BK][LDA];               // A^T tile
    __shared__ float Bs[BK][COUT];

    const float* root = L1 ? xin : g_h;
    float*       out  = L1 ? g_h : outp;

    int tid = threadIdx.x;
    int tx = tid & 15;
    int ty = tid >> 4;
    int rowBase = blockIdx.x * BM;

    float acc[TM][TN];
#pragma unroll
    for (int i = 0; i < TM; i++)
#pragma unroll
        for (int j = 0; j < TN; j++) acc[i][j] = 0.0f;

    for (int kk = 0; kk < 256; kk += BK) {
        bool first = kk < 128;
        int kOff = first ? kk : (kk - 128);
        const float* Asrc = first ? g_aggr : root;

        // load A tile (128 rows x 16 k), transposed into As[k][row]
#pragma unroll
        for (int it = 0; it < 2; it++) {
            int idx = tid + it * 256;           // 0..511
            int r = idx >> 2;
            int kq = (idx & 3) * 4;
            int grow = rowBase + r;
            float4 v = make_float4(0.f, 0.f, 0.f, 0.f);
            if (grow < NN)
                v = *(const float4*)(Asrc + (size_t)grow * 128 + kOff + kq);
            As[kq + 0][r] = v.x;
            As[kq + 1][r] = v.y;
            As[kq + 2][r] = v.z;
            As[kq + 3][r] = v.w;
        }

        // load B tile (16 x COUT)
        const float* W = first ? Wl : Wr;
        constexpr int BV = BK * COUT / 4;
#pragma unroll
        for (int it = 0; it < BV / 256; it++) {
            int idx = tid + it * 256;
            int r = idx / (COUT / 4);
            int c = (idx % (COUT / 4)) * 4;
            *(float4*)&Bs[r][c] = *(const float4*)(W + (size_t)(kOff + r) * COUT + c);
        }
        __syncthreads();

#pragma unroll
        for (int k = 0; k < BK; k++) {
            float a[TM], b[TN];
            float4 a0 = *(const float4*)&As[k][ty * TM];
            float4 a1 = *(const float4*)&As[k][ty * TM + 4];
            a[0] = a0.x; a[1] = a0.y; a[2] = a0.z; a[3] = a0.w;
            a[4] = a1.x; a[5] = a1.y; a[6] = a1.z; a[7] = a1.w;
            float4 b0 = *(const float4*)&Bs[k][tx * TN];
            b[0] = b0.x; b[1] = b0.y; b[2] = b0.z; b[3] = b0.w;
            if (TN == 8) {
                float4 b1 = *(const float4*)&Bs[k][tx * TN + 4];
                b[4] = b1.x; b[5] = b1.y; b[6] = b1.z; b[7] = b1.w;
            }
#pragma unroll
            for (int i = 0; i < TM; i++)
#pragma unroll
                for (int j = 0; j < TN; j++)
                    acc[i][j] = fmaf(a[i], b[j], acc[i][j]);
        }
        __syncthreads();
    }

    float bv[TN];
#pragma unroll
    for (int j = 0; j < TN; j++) bv[j] = bias[tx * TN + j];

#pragma unroll
    for (int i = 0; i < TM; i++) {
        int grow = rowBase + ty * TM + i;
        if (grow < NN) {
            float r[TN];
#pragma unroll
            for (int j = 0; j < TN; j++) {
                float v = acc[i][j] + bv[j];
                r[j] = L1 ? fmaxf(v, 0.0f) : v;
            }
            float* op = out + (size_t)grow * COUT + tx * TN;
#pragma unroll
            for (int j = 0; j < TN; j += 4)
                *(float4*)(op + j) = make_float4(r[j], r[j + 1], r[j + 2], r[j + 3]);
        }
    }
}

extern "C" void kernel_launch(void* const* d_in, const int* in_sizes, int n_in,
                              void* d_out, int out_size) {
    const float* x   = (const float*)d_in[0];
    const int*   ei  = (const int*)d_in[1];     // int64 in reference -> delivered as int32
    const float* W1l = (const float*)d_in[2];
    const float* b1  = (const float*)d_in[3];
    const float* W1r = (const float*)d_in[4];
    const float* W2l = (const float*)d_in[5];
    const float* b2  = (const float*)d_in[6];
    const float* W2r = (const float*)d_in[7];
    float*       out = (float*)d_out;

    const int* esrc = ei;
    const int* edst = ei + NE;

    const int edgeBlocks = (NE + 255) / 256;            // 6250
    const int nodeBlocks = (NN + 255) / 256;            // 391
    const int aggrBlocks = (NN * 32 + 255) / 256;       // 12500
    const int gemmBlocks = (NN + 127) / 128;            // 782

    // CSR build (once per call, used by both layers)
    k_zero_deg<<<nodeBlocks, 256>>>();
    k_count<<<edgeBlocks, 256>>>(edst);
    k_scan1<<<NBLK, SCAN_B>>>();
    k_scan2<<<1, 128>>>();
    k_scan3<<<NBLK, SCAN_B>>>();
    k_fill<<<edgeBlocks, 256>>>(esrc, edst);

    // Layer 1
    k_aggr<false><<<aggrBlocks, 256>>>(x);
    k_gemm<128, true><<<gemmBlocks, 256>>>(x, W1l, W1r, b1, nullptr);

    // Layer 2
    k_aggr<true><<<aggrBlocks, 256>>>(nullptr);
    k_gemm<64, false><<<gemmBlocks, 256>>>(nullptr, W2l, W2r, b2, out);
}

// round 5
// speedup vs baseline: 2.1782x; 1.0902x over previous
#include <cuda_runtime.h>
#include <cuda_bf16.h>
#include <mma.h>
#include <cstdint>

using namespace nvcuda;

#define NN 100000
#define NE 1600000
#define SCAN_B 1024
#define NBLK ((NN + SCAN_B - 1) / SCAN_B)   // 98

// ---------------- scratch (device globals; no allocation allowed) ----------------
__device__ __align__(16) float g_aggr[(size_t)NN * 128];   // 51.2 MB max-aggregated features
__device__ __align__(16) float g_h[(size_t)NN * 128];      // 51.2 MB hidden activations
__device__ int g_deg[NN];
__device__ int g_rowStart[NN + 1];
__device__ int g_cursor[NN];
__device__ int g_srcIdx[NE];
__device__ int g_blockTot[NBLK];
// Pre-split/transposed/padded weight images: per half {hi[128][NP], lo[128][NP]}
__device__ __align__(16) unsigned short g_Bimg1[2 * 2 * 128 * 136];  // layer1 NP=136
__device__ __align__(16) unsigned short g_Bimg2[2 * 2 * 128 * 72];   // layer2 NP=72

// split one float pair into packed bf16 hi and lo words
__device__ __forceinline__ void split2(float a, float b, uint32_t& h, uint32_t& l) {
    __nv_bfloat162 hb = __floats2bfloat162_rn(a, b);
    float2 hf = __bfloat1622float2(hb);
    __nv_bfloat162 lb = __floats2bfloat162_rn(a - hf.x, b - hf.y);
    h = *reinterpret_cast<uint32_t*>(&hb);
    l = *reinterpret_cast<uint32_t*>(&lb);
}

// ---------------- CSR build ----------------
__global__ void k_zero_deg() {
    int i = blockIdx.x * blockDim.x + threadIdx.x;
    if (i < NN) g_deg[i] = 0;
}
__global__ void k_count(const int* __restrict__ edst) {
    int i = blockIdx.x * blockDim.x + threadIdx.x;
    if (i < NE) atomicAdd(&g_deg[edst[i]], 1);
}
__global__ void __launch_bounds__(SCAN_B) k_scan1() {
    __shared__ int s[SCAN_B];
    int t = threadIdx.x;
    int i = blockIdx.x * SCAN_B + t;
    int v = (i < NN) ? g_deg[i] : 0;
    s[t] = v;
    __syncthreads();
#pragma unroll
    for (int off = 1; off < SCAN_B; off <<= 1) {
        int x = (t >= off) ? s[t - off] : 0;
        __syncthreads();
        s[t] += x;
        __syncthreads();
    }
    if (i < NN) g_rowStart[i] = s[t] - v;
    if (t == SCAN_B - 1) g_blockTot[blockIdx.x] = s[t];
}
__global__ void k_scan2() {
    __shared__ int s[128];
    int t = threadIdx.x;
    int v = (t < NBLK) ? g_blockTot[t] : 0;
    s[t] = v;
    __syncthreads();
#pragma unroll
    for (int off = 1; off < 128; off <<= 1) {
        int x = (t >= off) ? s[t - off] : 0;
        __syncthreads();
        s[t] += x;
        __syncthreads();
    }
    if (t < NBLK) g_blockTot[t] = s[t] - v;
}
__global__ void __launch_bounds__(SCAN_B) k_scan3() {
    int i = blockIdx.x * SCAN_B + threadIdx.x;
    if (i < NN) {
        int r = g_rowStart[i] + g_blockTot[blockIdx.x];
        g_rowStart[i] = r;
        g_cursor[i] = r;
    }
    if (i == 0) g_rowStart[NN] = NE;
}
__global__ void k_fill(const int* __restrict__ esrc, const int* __restrict__ edst) {
    int i = blockIdx.x * blockDim.x + threadIdx.x;
    if (i < NE) {
        int p = atomicAdd(&g_cursor[edst[i]], 1);
        g_srcIdx[p] = esrc[i];
    }
}

// ---------------- aggregation: warp per node, gather-max over CSR row ----------------
__device__ __forceinline__ float4 max4(float4 a, float4 b) {
    return make_float4(fmaxf(a.x, b.x), fmaxf(a.y, b.y), fmaxf(a.z, b.z), fmaxf(a.w, b.w));
}
template<bool USE_H>
__global__ void __launch_bounds__(256) k_aggr(const float* __restrict__ xin) {
    int w = (blockIdx.x * blockDim.x + threadIdx.x) >> 5;
    if (w >= NN) return;
    int lane = threadIdx.x & 31;
    const float* feat = USE_H ? g_h : xin;
    int beg = g_rowStart[w];
    int end = g_rowStart[w + 1];
    const float NEG = __int_as_float(0xff800000);
    float4 m = make_float4(NEG, NEG, NEG, NEG);
    int e = beg;
    for (; e + 4 <= end; e += 4) {
        int s0 = g_srcIdx[e + 0], s1 = g_srcIdx[e + 1];
        int s2 = g_srcIdx[e + 2], s3 = g_srcIdx[e + 3];
        float4 v0 = *(const float4*)(feat + (size_t)s0 * 128 + lane * 4);
        float4 v1 = *(const float4*)(feat + (size_t)s1 * 128 + lane * 4);
        float4 v2 = *(const float4*)(feat + (size_t)s2 * 128 + lane * 4);
        float4 v3 = *(const float4*)(feat + (size_t)s3 * 128 + lane * 4);
        m = max4(m, max4(max4(v0, v1), max4(v2, v3)));
    }
    for (; e < end; e++) {
        float4 v0 = *(const float4*)(feat + (size_t)g_srcIdx[e] * 128 + lane * 4);
        m = max4(m, v0);
    }
    if (beg == end) m = make_float4(0.f, 0.f, 0.f, 0.f);
    *(float4*)(g_aggr + (size_t)w * 128 + lane * 4) = m;
}

// ---------------- weight prep: split-bf16, B[k][n] padded row-major images ----------------
// Image layout: [half][hi/lo][k 0..127][n 0..NP), NP = COUT+8 (pad -> conflict-free ldmatrix)
template<int COUT>
__global__ void k_prepB(const float* __restrict__ Wl, const float* __restrict__ Wr,
                        unsigned short* __restrict__ dst) {
    constexpr int NP = COUT + 8;
    int idx = blockIdx.x * blockDim.x + threadIdx.x;
    if (idx >= 2 * 128 * COUT) return;
    int half = idx / (128 * COUT);
    int rem = idx - half * 128 * COUT;
    int k = rem / COUT;
    int n = rem - k * COUT;
    float f = (half ? Wr : Wl)[k * COUT + n];
    __nv_bfloat16 hb = __float2bfloat16(f);
    __nv_bfloat16 lb = __float2bfloat16(f - __bfloat162float(hb));
    dst[((size_t)(half * 2 + 0) * 128 + k) * NP + n] = *reinterpret_cast<unsigned short*>(&hb);
    dst[((size_t)(half * 2 + 1) * 128 + k) * NP + n] = *reinterpret_cast<unsigned short*>(&lb);
}

// ---------------- wmma split-bf16 fused SAGE GEMM ----------------
// out[r,:] = act( aggr[r,:] @ Wl + root[r,:] @ Wr + b )
// CTA = 128 rows x COUT cols, 8 warps in 4(row) x 2(col) grid, warp tile 32 x COUT/2.
// K = 2 halves of 128 (half0: aggr@Wl, half1: root@Wr). 3 MMA terms: AhBh + AhBl + AlBh.
template<int COUT, bool L1>
__global__ void __launch_bounds__(256) k_gemm_wm(const float* __restrict__ xin,
                                                 const unsigned short* __restrict__ Bimg,
                                                 const float* __restrict__ bias,
                                                 float* __restrict__ outp) {
    constexpr int NP = COUT + 8;
    constexpr int AP = 136;                 // A row pad (elements)
    constexpr int WN = COUT / 2;            // warp col span
    constexpr int NT = WN / 16;             // n-tiles per warp
    extern __shared__ char smem[];
    __nv_bfloat16* Ah = (__nv_bfloat16*)smem;
    __nv_bfloat16* Al = Ah + 128 * AP;
    __nv_bfloat16* Bh = Al + 128 * AP;
    __nv_bfloat16* Bl = Bh + 128 * NP;

    int tid = threadIdx.x, wid = tid >> 5, lane = tid & 31;
    int wm = wid & 3, wn = wid >> 2;
    int rowBase = blockIdx.x * 128;

    wmma::fragment<wmma::accumulator, 16, 16, 16, float> acc[2][NT];
#pragma unroll
    for (int i = 0; i < 2; i++)
#pragma unroll
        for (int j = 0; j < NT; j++) wmma::fill_fragment(acc[i][j], 0.0f);

    const float* rootSrc = L1 ? xin : g_h;
    int r = tid >> 1, kb = (tid & 1) << 6;
    int grow = rowBase + r;

    for (int half = 0; half < 2; half++) {
        const float* Asrc = half ? rootSrc : g_aggr;
        // stage A half: thread covers row r, k in [kb, kb+64), split to hi/lo bf16
        const float4* srcv = (grow < NN) ? (const float4*)(Asrc + (size_t)grow * 128 + kb) : nullptr;
#pragma unroll
        for (int i = 0; i < 16; i++) {
            float4 v = srcv ? srcv[i] : make_float4(0.f, 0.f, 0.f, 0.f);
            uint32_t h0, l0, h1, l1;
            split2(v.x, v.y, h0, l0);
            split2(v.z, v.w, h1, l1);
            *(uint2*)((unsigned short*)Ah + (size_t)r * AP + kb + i * 4) = make_uint2(h0, h1);
            *(uint2*)((unsigned short*)Al + (size_t)r * AP + kb + i * 4) = make_uint2(l0, l1);
        }
        // stage B half: straight copy of prepared [hi|lo] images
        {
            const uint4* src = (const uint4*)(Bimg + (size_t)half * 2 * 128 * NP);
            uint4* dst = (uint4*)Bh;
            const int n4 = 2 * 128 * NP * 2 / 16;
            for (int i = tid; i < n4; i += 256) dst[i] = src[i];
        }
        __syncthreads();

#pragma unroll
        for (int ks = 0; ks < 8; ks++) {
            int k0 = ks * 16;
            wmma::fragment<wmma::matrix_a, 16, 16, 16, __nv_bfloat16, wmma::row_major> fa_h[2], fa_l[2];
#pragma unroll
            for (int mt = 0; mt < 2; mt++) {
                const __nv_bfloat16* ap = Ah + (size_t)(wm * 32 + mt * 16) * AP + k0;
                wmma::load_matrix_sync(fa_h[mt], ap, AP);
                wmma::load_matrix_sync(fa_l[mt], Al + (size_t)(wm * 32 + mt * 16) * AP + k0, AP);
            }
#pragma unroll
            for (int nt = 0; nt < NT; nt++) {
                wmma::fragment<wmma::matrix_b, 16, 16, 16, __nv_bfloat16, wmma::row_major> fb_h, fb_l;
                const __nv_bfloat16* bp = Bh + (size_t)k0 * NP + wn * WN + nt * 16;
                wmma::load_matrix_sync(fb_h, bp, NP);
                wmma::load_matrix_sync(fb_l, Bl + (size_t)k0 * NP + wn * WN + nt * 16, NP);
                // interleave m-tiles per term -> accumulator dep distance >= 2
#pragma unroll
                for (int mt = 0; mt < 2; mt++) wmma::mma_sync(acc[mt][nt], fa_h[mt], fb_h, acc[mt][nt]);
#pragma unroll
                for (int mt = 0; mt < 2; mt++) wmma::mma_sync(acc[mt][nt], fa_h[mt], fb_l, acc[mt][nt]);
#pragma unroll
                for (int mt = 0; mt < 2; mt++) wmma::mma_sync(acc[mt][nt], fa_l[mt], fb_h, acc[mt][nt]);
            }
        }
        __syncthreads();
    }

    // ---- epilogue: bounce fragments through SMEM (reuse B region), fuse bias+ReLU ----
    constexpr int EW = WN + 4;
    float* bw = (float*)Bh + (size_t)wid * 32 * EW;
#pragma unroll
    for (int mt = 0; mt < 2; mt++)
#pragma unroll
        for (int nt = 0; nt < NT; nt++)
            wmma::store_matrix_sync(bw + mt * 16 * EW + nt * 16, acc[mt][nt], EW, wmma::mem_row_major);
    __syncwarp();

    int orow = rowBase + wm * 32 + lane;
    float* out = L1 ? g_h : outp;
    if (orow < NN) {
        float* op = out + (size_t)orow * COUT + wn * WN;
        const float* br = bw + (size_t)lane * EW;
#pragma unroll
        for (int c = 0; c < WN; c += 4) {
            float4 v = make_float4(br[c], br[c + 1], br[c + 2], br[c + 3]);
            v.x += bias[wn * WN + c + 0];
            v.y += bias[wn * WN + c + 1];
            v.z += bias[wn * WN + c + 2];
            v.w += bias[wn * WN + c + 3];
            if (L1) {
                v.x = fmaxf(v.x, 0.f); v.y = fmaxf(v.y, 0.f);
                v.z = fmaxf(v.z, 0.f); v.w = fmaxf(v.w, 0.f);
            }
            *(float4*)(op + c) = v;
        }
    }
}

extern "C" void kernel_launch(void* const* d_in, const int* in_sizes, int n_in,
                              void* d_out, int out_size) {
    const float* x   = (const float*)d_in[0];
    const int*   ei  = (const int*)d_in[1];
    const float* W1l = (const float*)d_in[2];
    const float* b1  = (const float*)d_in[3];
    const float* W1r = (const float*)d_in[4];
    const float* W2l = (const float*)d_in[5];
    const float* b2  = (const float*)d_in[6];
    const float* W2r = (const float*)d_in[7];
    float*       out = (float*)d_out;

    const int* esrc = ei;
    const int* edst = ei + NE;

    const int edgeBlocks = (NE + 255) / 256;
    const int nodeBlocks = (NN + 255) / 256;
    const int aggrBlocks = (NN * 32 + 255) / 256;
    const int gemmBlocks = (NN + 127) / 128;            // 782

    // dynamic SMEM: A(2 x 128 x 136) + B(2 x 128 x NP), bf16
    const int SMEM1 = (2 * 128 * 136 + 2 * 128 * 136) * 2;   // 139,264
    const int SMEM2 = (2 * 128 * 136 + 2 * 128 * 72) * 2;    // 106,496
    cudaFuncSetAttribute(k_gemm_wm<128, true>, cudaFuncAttributeMaxDynamicSharedMemorySize, SMEM1);
    cudaFuncSetAttribute(k_gemm_wm<64, false>, cudaFuncAttributeMaxDynamicSharedMemorySize, SMEM2);

    unsigned short* bimg1;
    unsigned short* bimg2;
    cudaGetSymbolAddress((void**)&bimg1, g_Bimg1);
    cudaGetSymbolAddress((void**)&bimg2, g_Bimg2);

    // CSR build
    k_zero_deg<<<nodeBlocks, 256>>>();
    k_count<<<edgeBlocks, 256>>>(edst);
    k_scan1<<<NBLK, SCAN_B>>>();
    k_scan2<<<1, 128>>>();
    k_scan3<<<NBLK, SCAN_B>>>();
    k_fill<<<edgeBlocks, 256>>>(esrc, edst);

    // weight prep
    k_prepB<128><<<(2 * 128 * 128 + 255) / 256, 256>>>(W1l, W1r, bimg1);
    k_prepB<64><<<(2 * 128 * 64 + 255) / 256, 256>>>(W2l, W2r, bimg2);

    // Layer 1
    k_aggr<false><<<aggrBlocks, 256>>>(x);
    k_gemm_wm<128, true><<<gemmBlocks, 256, SMEM1>>>(x, bimg1, b1, nullptr);

    // Layer 2
    k_aggr<true><<<aggrBlocks, 256>>>(nullptr);
    k_gemm_wm<64, false><<<gemmBlocks, 256, SMEM2>>>(nullptr, bimg2, b2, out);
}

// round 6
// speedup vs baseline: 2.1816x; 1.0015x over previous
#include <cuda_runtime.h>
#include <cuda_bf16.h>
#include <mma.h>
#include <cstdint>

using namespace nvcuda;

#define NN 100000
#define NE 1600000
#define SCAN_B 1024
#define NBLK ((NN + SCAN_B - 1) / SCAN_B)   // 98

// ---------------- scratch (device globals; no allocation allowed) ----------------
__device__ __align__(16) float g_aggr[(size_t)NN * 128];   // 51.2 MB max-aggregated features
__device__ __align__(16) float g_h[(size_t)NN * 128];      // 51.2 MB hidden activations
__device__ int g_deg[NN];
__device__ int g_rowStart[NN + 1];
__device__ int g_cursor[NN];
__device__ int g_srcIdx[NE];
__device__ int g_blockTot[NBLK];
// Pre-split/transposed/padded weight images: per half {hi[128][NP], lo[128][NP]}
__device__ __align__(16) unsigned short g_Bimg1[2 * 2 * 128 * 136];  // layer1 NP=136
__device__ __align__(16) unsigned short g_Bimg2[2 * 2 * 128 * 72];   // layer2 NP=72

// split one float pair into packed bf16 hi and lo words
__device__ __forceinline__ void split2(float a, float b, uint32_t& h, uint32_t& l) {
    __nv_bfloat162 hb = __floats2bfloat162_rn(a, b);
    float2 hf = __bfloat1622float2(hb);
    __nv_bfloat162 lb = __floats2bfloat162_rn(a - hf.x, b - hf.y);
    h = *reinterpret_cast<uint32_t*>(&hb);
    l = *reinterpret_cast<uint32_t*>(&lb);
}

// ---------------- CSR build ----------------
__global__ void k_zero_deg() {
    int i = blockIdx.x * blockDim.x + threadIdx.x;
    if (i < NN) g_deg[i] = 0;
}
__global__ void k_count(const int* __restrict__ edst) {
    int i = blockIdx.x * blockDim.x + threadIdx.x;
    if (i < NE) atomicAdd(&g_deg[edst[i]], 1);
}
__global__ void __launch_bounds__(SCAN_B) k_scan1() {
    __shared__ int s[SCAN_B];
    int t = threadIdx.x;
    int i = blockIdx.x * SCAN_B + t;
    int v = (i < NN) ? g_deg[i] : 0;
    s[t] = v;
    __syncthreads();
#pragma unroll
    for (int off = 1; off < SCAN_B; off <<= 1) {
        int x = (t >= off) ? s[t - off] : 0;
        __syncthreads();
        s[t] += x;
        __syncthreads();
    }
    if (i < NN) g_rowStart[i] = s[t] - v;
    if (t == SCAN_B - 1) g_blockTot[blockIdx.x] = s[t];
}
__global__ void k_scan2() {
    __shared__ int s[128];
    int t = threadIdx.x;
    int v = (t < NBLK) ? g_blockTot[t] : 0;
    s[t] = v;
    __syncthreads();
#pragma unroll
    for (int off = 1; off < 128; off <<= 1) {
        int x = (t >= off) ? s[t - off] : 0;
        __syncthreads();
        s[t] += x;
        __syncthreads();
    }
    if (t < NBLK) g_blockTot[t] = s[t] - v;
}
__global__ void __launch_bounds__(SCAN_B) k_scan3() {
    int i = blockIdx.x * SCAN_B + threadIdx.x;
    if (i < NN) {
        int r = g_rowStart[i] + g_blockTot[blockIdx.x];
        g_rowStart[i] = r;
        g_cursor[i] = r;
    }
    if (i == 0) g_rowStart[NN] = NE;
}
__global__ void k_fill(const int* __restrict__ esrc, const int* __restrict__ edst) {
    int i = blockIdx.x * blockDim.x + threadIdx.x;
    if (i < NE) {
        int p = atomicAdd(&g_cursor[edst[i]], 1);
        g_srcIdx[p] = esrc[i];
    }
}

// ---------------- aggregation: warp per node, gather-max over CSR row ----------------
__device__ __forceinline__ float4 max4(float4 a, float4 b) {
    return make_float4(fmaxf(a.x, b.x), fmaxf(a.y, b.y), fmaxf(a.z, b.z), fmaxf(a.w, b.w));
}
template<bool USE_H>
__global__ void __launch_bounds__(256) k_aggr(const float* __restrict__ xin) {
    int w = (blockIdx.x * blockDim.x + threadIdx.x) >> 5;
    if (w >= NN) return;
    int lane = threadIdx.x & 31;
    const float* feat = USE_H ? g_h : xin;
    int beg = g_rowStart[w];
    int end = g_rowStart[w + 1];
    const float NEG = __int_as_float(0xff800000);
    float4 m = make_float4(NEG, NEG, NEG, NEG);
    int e = beg;
    for (; e + 4 <= end; e += 4) {
        int s0 = g_srcIdx[e + 0], s1 = g_srcIdx[e + 1];
        int s2 = g_srcIdx[e + 2], s3 = g_srcIdx[e + 3];
        float4 v0 = *(const float4*)(feat + (size_t)s0 * 128 + lane * 4);
        float4 v1 = *(const float4*)(feat + (size_t)s1 * 128 + lane * 4);
        float4 v2 = *(const float4*)(feat + (size_t)s2 * 128 + lane * 4);
        float4 v3 = *(const float4*)(feat + (size_t)s3 * 128 + lane * 4);
        m = max4(m, max4(max4(v0, v1), max4(v2, v3)));
    }
    for (; e < end; e++) {
        float4 v0 = *(const float4*)(feat + (size_t)g_srcIdx[e] * 128 + lane * 4);
        m = max4(m, v0);
    }
    if (beg == end) m = make_float4(0.f, 0.f, 0.f, 0.f);
    *(float4*)(g_aggr + (size_t)w * 128 + lane * 4) = m;
}

// ---------------- weight prep: split-bf16, B[k][n] padded row-major images ----------------
// Image layout: [half][hi/lo][k 0..127][n 0..NP), NP = COUT+8 (pad -> conflict-free ldmatrix)
template<int COUT>
__global__ void k_prepB(const float* __restrict__ Wl, const float* __restrict__ Wr,
                        unsigned short* __restrict__ dst) {
    constexpr int NP = COUT + 8;
    int idx = blockIdx.x * blockDim.x + threadIdx.x;
    if (idx >= 2 * 128 * COUT) return;
    int half = idx / (128 * COUT);
    int rem = idx - half * 128 * COUT;
    int k = rem / COUT;
    int n = rem - k * COUT;
    float f = (half ? Wr : Wl)[k * COUT + n];
    __nv_bfloat16 hb = __float2bfloat16(f);
    __nv_bfloat16 lb = __float2bfloat16(f - __bfloat162float(hb));
    dst[((size_t)(half * 2 + 0) * 128 + k) * NP + n] = *reinterpret_cast<unsigned short*>(&hb);
    dst[((size_t)(half * 2 + 1) * 128 + k) * NP + n] = *reinterpret_cast<unsigned short*>(&lb);
}

// ---------------- wmma split-bf16 fused SAGE GEMM (BM=64 -> 2-3 CTAs/SM) ----------------
// out[r,:] = act( aggr[r,:] @ Wl + root[r,:] @ Wr + b )
// CTA = 64 rows x COUT cols, 8 warps in 2(row) x 4(col) grid, warp tile 32 x COUT/4.
// K = 2 halves of 128 (half0: aggr@Wl, half1: root@Wr). 3 MMA terms: AhBh + AhBl + AlBh.
template<int COUT, bool L1>
__global__ void __launch_bounds__(256) k_gemm_wm(const float* __restrict__ xin,
                                                 const unsigned short* __restrict__ Bimg,
                                                 const float* __restrict__ bias,
                                                 float* __restrict__ outp) {
    constexpr int BM = 64;
    constexpr int NP = COUT + 8;
    constexpr int AP = 136;                 // A row pad (elements)
    constexpr int WN = COUT / 4;            // warp col span (L1:32, L2:16)
    constexpr int NT = WN / 16;             // n-tiles per warp (L1:2, L2:1)
    extern __shared__ char smem[];
    __nv_bfloat16* Ah = (__nv_bfloat16*)smem;
    __nv_bfloat16* Al = Ah + BM * AP;
    __nv_bfloat16* Bh = Al + BM * AP;
    __nv_bfloat16* Bl = Bh + 128 * NP;

    int tid = threadIdx.x, wid = tid >> 5, lane = tid & 31;
    int wm = wid & 1, wn = wid >> 1;
    int rowBase = blockIdx.x * BM;

    wmma::fragment<wmma::accumulator, 16, 16, 16, float> acc[2][NT];
#pragma unroll
    for (int i = 0; i < 2; i++)
#pragma unroll
        for (int j = 0; j < NT; j++) wmma::fill_fragment(acc[i][j], 0.0f);

    const float* rootSrc = L1 ? xin : g_h;
    int r = tid >> 2, kq = (tid & 3) << 5;          // row 0..63, k-quarter base 0/32/64/96
    int grow = rowBase + r;

    for (int half = 0; half < 2; half++) {
        const float* Asrc = half ? rootSrc : g_aggr;
        // stage A half: thread covers row r, k in [kq, kq+32), split to hi/lo bf16
        const float4* srcv = (grow < NN) ? (const float4*)(Asrc + (size_t)grow * 128 + kq) : nullptr;
#pragma unroll
        for (int i = 0; i < 8; i++) {
            float4 v = srcv ? srcv[i] : make_float4(0.f, 0.f, 0.f, 0.f);
            uint32_t h0, l0, h1, l1;
            split2(v.x, v.y, h0, l0);
            split2(v.z, v.w, h1, l1);
            *(uint2*)((unsigned short*)Ah + (size_t)r * AP + kq + i * 4) = make_uint2(h0, h1);
            *(uint2*)((unsigned short*)Al + (size_t)r * AP + kq + i * 4) = make_uint2(l0, l1);
        }
        // stage B half: straight copy of prepared [hi|lo] images
        {
            const uint4* src = (const uint4*)(Bimg + (size_t)half * 2 * 128 * NP);
            uint4* dst = (uint4*)Bh;
            const int n4 = 2 * 128 * NP * 2 / 16;
            for (int i = tid; i < n4; i += 256) dst[i] = src[i];
        }
        __syncthreads();

#pragma unroll
        for (int ks = 0; ks < 8; ks++) {
            int k0 = ks * 16;
            wmma::fragment<wmma::matrix_a, 16, 16, 16, __nv_bfloat16, wmma::row_major> fa_h[2], fa_l[2];
#pragma unroll
            for (int mt = 0; mt < 2; mt++) {
                wmma::load_matrix_sync(fa_h[mt], Ah + (size_t)(wm * 32 + mt * 16) * AP + k0, AP);
                wmma::load_matrix_sync(fa_l[mt], Al + (size_t)(wm * 32 + mt * 16) * AP + k0, AP);
            }
#pragma unroll
            for (int nt = 0; nt < NT; nt++) {
                wmma::fragment<wmma::matrix_b, 16, 16, 16, __nv_bfloat16, wmma::row_major> fb_h, fb_l;
                wmma::load_matrix_sync(fb_h, Bh + (size_t)k0 * NP + wn * WN + nt * 16, NP);
                wmma::load_matrix_sync(fb_l, Bl + (size_t)k0 * NP + wn * WN + nt * 16, NP);
                // interleave m-tiles per term -> accumulator dep distance >= 2
#pragma unroll
                for (int mt = 0; mt < 2; mt++) wmma::mma_sync(acc[mt][nt], fa_h[mt], fb_h, acc[mt][nt]);
#pragma unroll
                for (int mt = 0; mt < 2; mt++) wmma::mma_sync(acc[mt][nt], fa_h[mt], fb_l, acc[mt][nt]);
#pragma unroll
                for (int mt = 0; mt < 2; mt++) wmma::mma_sync(acc[mt][nt], fa_l[mt], fb_h, acc[mt][nt]);
            }
        }
        __syncthreads();
    }

    // ---- epilogue: bounce fragments through SMEM (reuse B region), fuse bias+ReLU ----
    constexpr int EW = WN + 4;
    float* bw = (float*)Bh + (size_t)wid * 32 * EW;
#pragma unroll
    for (int mt = 0; mt < 2; mt++)
#pragma unroll
        for (int nt = 0; nt < NT; nt++)
            wmma::store_matrix_sync(bw + mt * 16 * EW + nt * 16, acc[mt][nt], EW, wmma::mem_row_major);
    __syncwarp();

    int orow = rowBase + wm * 32 + lane;
    float* out = L1 ? g_h : outp;
    if (orow < NN) {
        float* op = out + (size_t)orow * COUT + wn * WN;
        const float* br = bw + (size_t)lane * EW;
#pragma unroll
        for (int c = 0; c < WN; c += 4) {
            float4 v = make_float4(br[c], br[c + 1], br[c + 2], br[c + 3]);
            v.x += bias[wn * WN + c + 0];
            v.y += bias[wn * WN + c + 1];
            v.z += bias[wn * WN + c + 2];
            v.w += bias[wn * WN + c + 3];
            if (L1) {
                v.x = fmaxf(v.x, 0.f); v.y = fmaxf(v.y, 0.f);
                v.z = fmaxf(v.z, 0.f); v.w = fmaxf(v.w, 0.f);
            }
            *(float4*)(op + c) = v;
        }
    }
}

extern "C" void kernel_launch(void* const* d_in, const int* in_sizes, int n_in,
                              void* d_out, int out_size) {
    const float* x   = (const float*)d_in[0];
    const int*   ei  = (const int*)d_in[1];
    const float* W1l = (const float*)d_in[2];
    const float* b1  = (const float*)d_in[3];
    const float* W1r = (const float*)d_in[4];
    const float* W2l = (const float*)d_in[5];
    const float* b2  = (const float*)d_in[6];
    const float* W2r = (const float*)d_in[7];
    float*       out = (float*)d_out;

    const int* esrc = ei;
    const int* edst = ei + NE;

    const int edgeBlocks = (NE + 255) / 256;
    const int nodeBlocks = (NN + 255) / 256;
    const int aggrBlocks = (NN * 32 + 255) / 256;
    const int gemmBlocks = (NN + 63) / 64;              // 1563

    // dynamic SMEM: A(2 x 64 x 136) + B(2 x 128 x NP), bf16
    const int SMEM1 = (2 * 64 * 136 + 2 * 128 * 136) * 2;   // 104,448 -> 2 CTAs/SM
    const int SMEM2 = (2 * 64 * 136 + 2 * 128 * 72) * 2;    //  71,680 -> 3 CTAs/SM
    cudaFuncSetAttribute(k_gemm_wm<128, true>, cudaFuncAttributeMaxDynamicSharedMemorySize, SMEM1);
    cudaFuncSetAttribute(k_gemm_wm<64, false>, cudaFuncAttributeMaxDynamicSharedMemorySize, SMEM2);

    unsigned short* bimg1;
    unsigned short* bimg2;
    cudaGetSymbolAddress((void**)&bimg1, g_Bimg1);
    cudaGetSymbolAddress((void**)&bimg2, g_Bimg2);

    // CSR build
    k_zero_deg<<<nodeBlocks, 256>>>();
    k_count<<<edgeBlocks, 256>>>(edst);
    k_scan1<<<NBLK, SCAN_B>>>();
    k_scan2<<<1, 128>>>();
    k_scan3<<<NBLK, SCAN_B>>>();
    k_fill<<<edgeBlocks, 256>>>(esrc, edst);

    // weight prep
    k_prepB<128><<<(2 * 128 * 128 + 255) / 256, 256>>>(W1l, W1r, bimg1);
    k_prepB<64><<<(2 * 128 * 64 + 255) / 256, 256>>>(W2l, W2r, bimg2);

    // Layer 1
    k_aggr<false><<<aggrBlocks, 256>>>(x);
    k_gemm_wm<128, true><<<gemmBlocks, 256, SMEM1>>>(x, bimg1, b1, nullptr);

    // Layer 2
    k_aggr<true><<<aggrBlocks, 256>>>(nullptr);
    k_gemm_wm<64, false><<<gemmBlocks, 256, SMEM2>>>(nullptr, bimg2, b2, out);
}